// round 2
// baseline (speedup 1.0000x reference)
#include <cuda_runtime.h>
#include <cstdint>
#include <cstddef>

// Problem constants
#define B_   8
#define N_   4096
#define C_   256
#define CI_  32
#define BM   64
#define BN   64
#define TSTR 68   // padded row stride (floats) for transposed k-major tiles

// Scratch (static device globals — no runtime allocation allowed)
__device__ float g_q[B_ * N_ * CI_];
__device__ float g_k[B_ * N_ * CI_];
__device__ float g_v[B_ * N_ * CI_];

// ---------------- packed fp32x2 helpers (Blackwell FFMA2 path) ----------------
__device__ __forceinline__ uint64_t pk2(float lo, float hi) {
    uint64_t r; asm("mov.b64 %0,{%1,%2};" : "=l"(r) : "f"(lo), "f"(hi)); return r;
}
__device__ __forceinline__ uint64_t bc2(float v) { return pk2(v, v); }
__device__ __forceinline__ void up2(uint64_t p, float &lo, float &hi) {
    asm("mov.b64 {%0,%1},%2;" : "=f"(lo), "=f"(hi) : "l"(p));
}
__device__ __forceinline__ uint64_t f2fma(uint64_t a, uint64_t b, uint64_t c) {
    uint64_t d; asm("fma.rn.f32x2 %0,%1,%2,%3;" : "=l"(d) : "l"(a), "l"(b), "l"(c)); return d;
}
__device__ __forceinline__ uint64_t f2mul(uint64_t a, uint64_t b) {
    uint64_t d; asm("mul.rn.f32x2 %0,%1,%2;" : "=l"(d) : "l"(a), "l"(b)); return d;
}

// ---------------- Kernel 1: fused channel projections (1x1 convs) ----------------
// grid.x: 512 row-tiles of 64 rows over B*N = 32768 rows; grid.y: {q,k,v}
__global__ void __launch_bounds__(256, 2) proj_kernel(
    const float* __restrict__ x, const float* __restrict__ y,
    const float* __restrict__ Wfy, const float* __restrict__ Wgx,
    const float* __restrict__ Whx)
{
    __shared__ float sA[32 * TSTR];  // A^T chunk: [k][row]
    __shared__ float sW[32 * 32];    // W chunk:   [k][col]

    const int tid = threadIdx.x;
    const int tx  = tid & 15;
    const int ty  = tid >> 4;

    const float* A; const float* W; float* out;
    if (blockIdx.y == 0)      { A = y; W = Wfy; out = g_q; }
    else if (blockIdx.y == 1) { A = x; W = Wgx; out = g_k; }
    else                      { A = x; W = Whx; out = g_v; }

    const int row0 = blockIdx.x * BM;

    uint64_t acc[4] = {0ull, 0ull, 0ull, 0ull};  // 4 rows x (2 packed cols)

    for (int kc = 0; kc < C_; kc += 32) {
        __syncthreads();
        // Load A chunk transposed: 64 rows x 32 k  -> sA[k][row]
        #pragma unroll
        for (int t = 0; t < 8; t++) {
            int idx = tid + t * 256;
            int r = idx >> 5;
            int k = idx & 31;
            sA[k * TSTR + r] = A[(size_t)(row0 + r) * C_ + kc + k];
        }
        // Load W chunk: 32 k x 32 cols
        #pragma unroll
        for (int t = 0; t < 4; t++) {
            int idx = tid + t * 256;
            int kr = idx >> 5;
            int c = idx & 31;
            sW[kr * 32 + c] = W[(size_t)(kc + kr) * CI_ + c];
        }
        __syncthreads();

        #pragma unroll 8
        for (int k = 0; k < 32; k++) {
            float4 a4 = *(const float4*)&sA[k * TSTR + ty * 4];
            uint64_t b = *(const uint64_t*)&sW[k * 32 + 2 * tx];
            acc[0] = f2fma(bc2(a4.x), b, acc[0]);
            acc[1] = f2fma(bc2(a4.y), b, acc[1]);
            acc[2] = f2fma(bc2(a4.z), b, acc[2]);
            acc[3] = f2fma(bc2(a4.w), b, acc[3]);
        }
    }

    #pragma unroll
    for (int i = 0; i < 4; i++) {
        *(uint64_t*)&out[(size_t)(row0 + ty * 4 + i) * CI_ + 2 * tx] = acc[i];
    }
}

// ---------------- Kernel 2: flash attention + fused epilogue ----------------
// One CTA per (query-block of 64 rows, batch). 256 threads.
// Thread grid 16x16: rows ty*4..+4, S cols {2tx, 2tx+1, 2tx+32, 2tx+33}.
// Shared layout (floats), main phase:
//   sQ  [32][TSTR]  @ 0        (Q^T)
//   sK  [32][TSTR]  @ 2176     (K^T)
//   sV  [64][32]    @ 4352
//   sP  [64][TSTR]  @ 6400     (P^T: [key][row])
// Epilogue phase (overlaid):
//   sOt [32][TSTR]  @ 0        (O^T: [ci][row])
//   sWo [32][256]   @ 2176
__global__ void __launch_bounds__(256, 2) attn_kernel(
    const float* __restrict__ x, const float* __restrict__ Wout,
    const float* __restrict__ sigma_p, float* __restrict__ outp)
{
    __shared__ float smem[10752];  // 42 KB
    float* sQ  = smem;
    float* sK  = smem + 32 * TSTR;
    float* sV  = smem + 2 * 32 * TSTR;
    float* sP  = smem + 2 * 32 * TSTR + BN * CI_;
    float* sOt = smem;
    float* sWo = smem + 32 * TSTR;

    const int tid = threadIdx.x;
    const int tx  = tid & 15;
    const int ty  = tid >> 4;
    const int qb  = blockIdx.x;   // query block (0..63)
    const int b   = blockIdx.y;   // batch

    // Load Q tile transposed (once)
    const float* qbase = g_q + ((size_t)b * N_ + qb * BM) * CI_;
    #pragma unroll
    for (int t = 0; t < 8; t++) {
        int idx = tid + t * 256;
        int r = idx >> 5;
        int k = idx & 31;
        sQ[k * TSTR + r] = qbase[r * CI_ + k];
    }

    float m_run[4], l_run[4];
    uint64_t oacc[4];  // O: 4 rows x (cols 2tx,2tx+1 packed)
    #pragma unroll
    for (int i = 0; i < 4; i++) { m_run[i] = -1e30f; l_run[i] = 0.0f; oacc[i] = 0ull; }

    for (int kb = 0; kb < N_; kb += BN) {
        __syncthreads();  // previous iteration's P/V reads done
        // Load K tile transposed
        const float* kbase = g_k + ((size_t)b * N_ + kb) * CI_;
        #pragma unroll
        for (int t = 0; t < 8; t++) {
            int idx = tid + t * 256;
            int r = idx >> 5;
            int k = idx & 31;
            sK[k * TSTR + r] = kbase[r * CI_ + k];
        }
        // Load V tile (row-major [key][ci])
        const float4* vbase = (const float4*)(g_v + ((size_t)b * N_ + kb) * CI_);
        #pragma unroll
        for (int t = 0; t < 2; t++) {
            ((float4*)sV)[tid + t * 256] = vbase[tid + t * 256];
        }
        __syncthreads();

        // ---- S = Q K^T (64x64, k=32) ----
        uint64_t sacc[4][2];
        #pragma unroll
        for (int i = 0; i < 4; i++) { sacc[i][0] = 0ull; sacc[i][1] = 0ull; }
        #pragma unroll 8
        for (int k = 0; k < 32; k++) {
            float4 q4   = *(const float4*)&sQ[k * TSTR + ty * 4];
            uint64_t b0 = *(const uint64_t*)&sK[k * TSTR + 2 * tx];
            uint64_t b1 = *(const uint64_t*)&sK[k * TSTR + 2 * tx + 32];
            uint64_t a0 = bc2(q4.x), a1 = bc2(q4.y), a2 = bc2(q4.z), a3 = bc2(q4.w);
            sacc[0][0] = f2fma(a0, b0, sacc[0][0]); sacc[0][1] = f2fma(a0, b1, sacc[0][1]);
            sacc[1][0] = f2fma(a1, b0, sacc[1][0]); sacc[1][1] = f2fma(a1, b1, sacc[1][1]);
            sacc[2][0] = f2fma(a2, b0, sacc[2][0]); sacc[2][1] = f2fma(a2, b1, sacc[2][1]);
            sacc[3][0] = f2fma(a3, b0, sacc[3][0]); sacc[3][1] = f2fma(a3, b1, sacc[3][1]);
        }

        // ---- online softmax ----
        float s[4][4];
        #pragma unroll
        for (int i = 0; i < 4; i++) {
            up2(sacc[i][0], s[i][0], s[i][1]);
            up2(sacc[i][1], s[i][2], s[i][3]);
        }
        #pragma unroll
        for (int i = 0; i < 4; i++) {
            float rm = fmaxf(fmaxf(s[i][0], s[i][1]), fmaxf(s[i][2], s[i][3]));
            rm = fmaxf(rm, __shfl_xor_sync(0xffffffffu, rm, 8, 16));
            rm = fmaxf(rm, __shfl_xor_sync(0xffffffffu, rm, 4, 16));
            rm = fmaxf(rm, __shfl_xor_sync(0xffffffffu, rm, 2, 16));
            rm = fmaxf(rm, __shfl_xor_sync(0xffffffffu, rm, 1, 16));
            float mnew  = fmaxf(m_run[i], rm);
            float alpha = __expf(m_run[i] - mnew);
            m_run[i] = mnew;
            float ps = 0.0f;
            #pragma unroll
            for (int j = 0; j < 4; j++) {
                float p = __expf(s[i][j] - mnew);
                s[i][j] = p;
                ps += p;
            }
            ps += __shfl_xor_sync(0xffffffffu, ps, 8, 16);
            ps += __shfl_xor_sync(0xffffffffu, ps, 4, 16);
            ps += __shfl_xor_sync(0xffffffffu, ps, 2, 16);
            ps += __shfl_xor_sync(0xffffffffu, ps, 1, 16);
            l_run[i] = l_run[i] * alpha + ps;
            oacc[i]  = f2mul(oacc[i], bc2(alpha));
        }

        // ---- stage P^T[key][row] ----
        #pragma unroll
        for (int jj = 0; jj < 4; jj++) {
            int c = 2 * tx + (jj >> 1) * 32 + (jj & 1);
            float4 pv = make_float4(s[0][jj], s[1][jj], s[2][jj], s[3][jj]);
            *(float4*)&sP[c * TSTR + ty * 4] = pv;
        }
        __syncthreads();

        // ---- O += P V (64x32, k=64) ----
        #pragma unroll 8
        for (int kk = 0; kk < BN; kk++) {
            float4 p4   = *(const float4*)&sP[kk * TSTR + ty * 4];
            uint64_t v2 = *(const uint64_t*)&sV[kk * CI_ + 2 * tx];
            oacc[0] = f2fma(bc2(p4.x), v2, oacc[0]);
            oacc[1] = f2fma(bc2(p4.y), v2, oacc[1]);
            oacc[2] = f2fma(bc2(p4.z), v2, oacc[2]);
            oacc[3] = f2fma(bc2(p4.w), v2, oacc[3]);
        }
    }

    // normalize rows
    #pragma unroll
    for (int i = 0; i < 4; i++) {
        float inv = 1.0f / l_run[i];
        oacc[i] = f2mul(oacc[i], bc2(inv));
    }

    __syncthreads();  // everyone done with main-phase shared

    // stage O^T[ci][row]
    {
        float olo[4], ohi[4];
        #pragma unroll
        for (int i = 0; i < 4; i++) up2(oacc[i], olo[i], ohi[i]);
        *(float4*)&sOt[(2 * tx)     * TSTR + ty * 4] = make_float4(olo[0], olo[1], olo[2], olo[3]);
        *(float4*)&sOt[(2 * tx + 1) * TSTR + ty * 4] = make_float4(ohi[0], ohi[1], ohi[2], ohi[3]);
    }
    // load W_out [32][256]
    #pragma unroll
    for (int t = 0; t < 8; t++) {
        ((float4*)sWo)[tid + t * 256] = ((const float4*)Wout)[tid + t * 256];
    }
    __syncthreads();

    // ---- epilogue GEMM: out = x + sigma * (O @ W_out) ----
    // thread: rows ty*4..+4, cols {2tx + 32j}, j=0..7 (paired)
    uint64_t eacc[4][8];
    #pragma unroll
    for (int i = 0; i < 4; i++)
        #pragma unroll
        for (int j = 0; j < 8; j++) eacc[i][j] = 0ull;

    #pragma unroll 4
    for (int c = 0; c < CI_; c++) {
        float4 o4 = *(const float4*)&sOt[c * TSTR + ty * 4];
        uint64_t a0 = bc2(o4.x), a1 = bc2(o4.y), a2 = bc2(o4.z), a3 = bc2(o4.w);
        #pragma unroll
        for (int j = 0; j < 8; j++) {
            uint64_t w2 = *(const uint64_t*)&sWo[c * C_ + 2 * tx + 32 * j];
            eacc[0][j] = f2fma(a0, w2, eacc[0][j]);
            eacc[1][j] = f2fma(a1, w2, eacc[1][j]);
            eacc[2][j] = f2fma(a2, w2, eacc[2][j]);
            eacc[3][j] = f2fma(a3, w2, eacc[3][j]);
        }
    }

    const float sig = sigma_p[0];
    const uint64_t sig2 = bc2(sig);
    #pragma unroll
    for (int i = 0; i < 4; i++) {
        size_t rowoff = ((size_t)b * N_ + qb * BM + ty * 4 + i) * C_;
        #pragma unroll
        for (int j = 0; j < 8; j++) {
            size_t off = rowoff + 2 * tx + 32 * j;
            uint64_t x2 = *(const uint64_t*)&x[off];
            uint64_t r  = f2fma(sig2, eacc[i][j], x2);
            *(uint64_t*)&outp[off] = r;
        }
    }
}

// ---------------- launch ----------------
extern "C" void kernel_launch(void* const* d_in, const int* in_sizes, int n_in,
                              void* d_out, int out_size)
{
    (void)in_sizes; (void)n_in; (void)out_size;
    const float* x     = (const float*)d_in[0];
    const float* y     = (const float*)d_in[1];
    const float* Wfy   = (const float*)d_in[2];
    const float* Wgx   = (const float*)d_in[3];
    const float* Whx   = (const float*)d_in[4];
    const float* Wout  = (const float*)d_in[5];
    const float* sigma = (const float*)d_in[6];
    float* out = (float*)d_out;

    proj_kernel<<<dim3((B_ * N_) / BM, 3), 256>>>(x, y, Wfy, Wgx, Whx);
    attn_kernel<<<dim3(N_ / BM, B_), 256>>>(x, Wout, sigma, out);
}

// round 6
// speedup vs baseline: 2.9699x; 2.9699x over previous
#include <cuda_runtime.h>
#include <cuda_bf16.h>
#include <cstdint>
#include <cstddef>

#define B_   8
#define N_   4096
#define C_   256
#define CI_  32

// Global bf16 scratch written by proj_kernel:
// g_q/g_k: per global row r (= b*4096+n): 128 bytes = 64 bf16: ci 0..31 hi at bytes 0..63, lo at 64..127
// g_v: V^T per batch: [64 rows: ci 0..31 hi, 32..63 lo][4096 keys] bf16
__device__ uint4 g_q[262144];
__device__ uint4 g_k[262144];
__device__ uint4 g_v[262144];

// ---------------- fp32x2 helpers ----------------
__device__ __forceinline__ uint64_t pk2(float lo, float hi) {
    uint64_t r; asm("mov.b64 %0,{%1,%2};" : "=l"(r) : "f"(lo), "f"(hi)); return r;
}
__device__ __forceinline__ uint64_t bc2(float v) { return pk2(v, v); }
__device__ __forceinline__ void up2(uint64_t p, float &lo, float &hi) {
    asm("mov.b64 {%0,%1},%2;" : "=f"(lo), "=f"(hi) : "l"(p));
}
__device__ __forceinline__ uint64_t f2fma(uint64_t a, uint64_t b, uint64_t c) {
    uint64_t d; asm("fma.rn.f32x2 %0,%1,%2,%3;" : "=l"(d) : "l"(a), "l"(b), "l"(c)); return d;
}

// ---------------- misc helpers ----------------
__device__ __forceinline__ uint32_t smem_u32(const void* p) {
    uint32_t a;
    asm("{ .reg .u64 t; cvta.to.shared.u64 t, %1; cvt.u32.u64 %0, t; }" : "=r"(a) : "l"(p));
    return a;
}
// pack two fp32 -> bf16x2; 'lo' in low 16 bits
__device__ __forceinline__ uint32_t pack2bf(float lo, float hi) {
    uint32_t r; asm("cvt.rn.bf16x2.f32 %0, %1, %2;" : "=r"(r) : "f"(hi), "f"(lo)); return r;
}
__device__ __forceinline__ float ex2(float t) {
    float p; asm("ex2.approx.ftz.f32 %0, %1;" : "=f"(p) : "f"(t)); return p;
}

// byte-column swizzle within a 128B row (SW128 pattern)
#define SWC(row, colb) ((uint32_t)((colb) ^ (((row) & 7) << 4)))

#define CP16(dst, src) \
    asm volatile("cp.async.ca.shared.global [%0], [%1], 16;" :: "r"(dst), "l"(src))
#define CPCOMMIT() asm volatile("cp.async.commit_group;" ::: "memory")
#define CPWAIT0()  asm volatile("cp.async.wait_group 0;" ::: "memory")

__device__ __forceinline__ void ldsm_x4(uint32_t* r, uint32_t addr) {
    asm volatile("ldmatrix.sync.aligned.m8n8.x4.shared.b16 {%0,%1,%2,%3}, [%4];"
        : "=r"(r[0]), "=r"(r[1]), "=r"(r[2]), "=r"(r[3]) : "r"(addr));
}
__device__ __forceinline__ void ldsm_x2(uint32_t* r, uint32_t addr) {
    asm volatile("ldmatrix.sync.aligned.m8n8.x2.shared.b16 {%0,%1}, [%2];"
        : "=r"(r[0]), "=r"(r[1]) : "r"(addr));
}
__device__ __forceinline__ void mma16816(float* c, const uint32_t* a, const uint32_t* b) {
    asm volatile(
        "mma.sync.aligned.m16n8k16.row.col.f32.bf16.bf16.f32 "
        "{%0,%1,%2,%3}, {%4,%5,%6,%7}, {%8,%9}, {%0,%1,%2,%3};"
        : "+f"(c[0]), "+f"(c[1]), "+f"(c[2]), "+f"(c[3])
        : "r"(a[0]), "r"(a[1]), "r"(a[2]), "r"(a[3]), "r"(b[0]), "r"(b[1]));
}

// ---------------- Kernel 1: fused projections -> bf16 hi/lo global tiles ----------------
#define TSTR 68
__global__ void __launch_bounds__(256, 2) proj_kernel(
    const float* __restrict__ x, const float* __restrict__ y,
    const float* __restrict__ Wfy, const float* __restrict__ Wgx,
    const float* __restrict__ Whx)
{
    __shared__ float sA[32 * TSTR];
    __shared__ float sW[32 * 32];

    const int tid = threadIdx.x;
    const int tx  = tid & 15;
    const int ty  = tid >> 4;

    const float* A; const float* W;
    if (blockIdx.y == 0)      { A = y; W = Wfy; }
    else if (blockIdx.y == 1) { A = x; W = Wgx; }
    else                      { A = x; W = Whx; }

    const int row0 = blockIdx.x * 64;
    uint64_t acc[4] = {0ull, 0ull, 0ull, 0ull};

    for (int kc = 0; kc < C_; kc += 32) {
        __syncthreads();
        #pragma unroll
        for (int t = 0; t < 8; t++) {
            int idx = tid + t * 256;
            int r = idx >> 5, k = idx & 31;
            sA[k * TSTR + r] = A[(size_t)(row0 + r) * C_ + kc + k];
        }
        #pragma unroll
        for (int t = 0; t < 4; t++) {
            int idx = tid + t * 256;
            int kr = idx >> 5, c = idx & 31;
            sW[kr * 32 + c] = W[(size_t)(kc + kr) * CI_ + c];
        }
        __syncthreads();
        #pragma unroll 8
        for (int k = 0; k < 32; k++) {
            float4 a4 = *(const float4*)&sA[k * TSTR + ty * 4];
            uint64_t b = *(const uint64_t*)&sW[k * 32 + 2 * tx];
            acc[0] = f2fma(bc2(a4.x), b, acc[0]);
            acc[1] = f2fma(bc2(a4.y), b, acc[1]);
            acc[2] = f2fma(bc2(a4.z), b, acc[2]);
            acc[3] = f2fma(bc2(a4.w), b, acc[3]);
        }
    }

    if (blockIdx.y < 2) {
        uint32_t* out = (blockIdx.y == 0) ? (uint32_t*)g_q : (uint32_t*)g_k;
        #pragma unroll
        for (int i = 0; i < 4; i++) {
            size_t r = (size_t)(row0 + ty * 4 + i);
            float v0, v1; up2(acc[i], v0, v1);
            uint32_t hw = pack2bf(v0, v1);
            float h0 = __uint_as_float(hw << 16);
            float h1 = __uint_as_float(hw & 0xffff0000u);
            uint32_t lw = pack2bf(v0 - h0, v1 - h1);
            out[r * 32 + tx]      = hw;   // ci 2tx,2tx+1 hi
            out[r * 32 + 16 + tx] = lw;   // lo
        }
    } else {
        unsigned short* out = (unsigned short*)g_v;
        #pragma unroll
        for (int i = 0; i < 4; i++) {
            int rg = row0 + ty * 4 + i;
            int bq = rg >> 12, key = rg & 4095;
            float v0, v1; up2(acc[i], v0, v1);
            #pragma unroll
            for (int e = 0; e < 2; e++) {
                int ci = 2 * tx + e;
                float v = e ? v1 : v0;
                uint32_t hb = pack2bf(v, v) & 0xffffu;
                float hf = __uint_as_float(hb << 16);
                uint32_t lb = pack2bf(v - hf, v - hf) & 0xffffu;
                out[((size_t)(bq * 64 + ci)      * 4096) + key] = (unsigned short)hb;
                out[((size_t)(bq * 64 + 32 + ci) * 4096) + key] = (unsigned short)lb;
            }
        }
    }
}

// ---------------- Kernel 2: warp-MMA flash attention + fused epilogue ----------------
// smem: sQ @0 (16KB); buf0 @16384 (K 8KB + V 8KB); buf1 @32768 (16KB)
// epilogue overlay: sOt fp32 @0 (32 x 132), sW fp32 @17408 (32KB). Total 50176.
#define SM_BUF0 16384
#define SM_W    17408
#define SM_TOT  50176

__device__ __forceinline__ void prefetch_kv(int b, int kb, uint32_t bufbase, int tid) {
    #pragma unroll
    for (int t = 0; t < 4; t++) {
        int idx = tid + t * 256;
        if (idx < 512) {  // K tile: 64 key-rows x 128B
            int row = idx >> 3, ch = idx & 7;
            uint32_t dst = bufbase + row * 128 + SWC(row, ch * 16);
            const uint4* src = g_k + ((size_t)(b * 4096 + kb * 64 + row) * 8 + ch);
            CP16(dst, src);
        } else {          // V tile: 64 ci-rows x 128B (64 keys)
            int j = idx - 512;
            int row = j >> 3, ch = j & 7;
            uint32_t dst = bufbase + 8192 + row * 128 + SWC(row, ch * 16);
            const uint4* src = g_v + ((size_t)(b * 64 + row) * 512 + (size_t)kb * 8 + ch);
            CP16(dst, src);
        }
    }
}

__global__ void __launch_bounds__(256, 2) attn_kernel(
    const float* __restrict__ x, const float* __restrict__ Wout,
    const float* __restrict__ sigma_p, float* __restrict__ outp)
{
    extern __shared__ unsigned char sm[];
    const uint32_t sb = smem_u32(sm);

    const int tid  = threadIdx.x;
    const int lane = tid & 31;
    const int w    = tid >> 5;       // warp 0..7 -> query rows 16w..16w+15
    const int qt   = blockIdx.x;
    const int b    = blockIdx.y;
    const int qr0  = w * 16;

    // kick off K/V block 0 prefetch
    prefetch_kv(b, 0, sb + SM_BUF0, tid);
    CPCOMMIT();

    // load Q tile (swizzled)
    {
        const uint4* src = g_q + (size_t)(b * 4096 + qt * 128) * 8;
        #pragma unroll
        for (int t = 0; t < 4; t++) {
            int idx = tid + t * 256;
            int row = idx >> 3, ch = idx & 7;
            *(uint4*)(sm + row * 128 + SWC(row, ch * 16)) = src[idx];
        }
    }
    __syncthreads();

    // Q fragments: [img hi/lo][kstep][4 regs]
    uint32_t qf[2][2][4];
    {
        int r = lane & 15;
        int c16 = (lane >= 16) ? 16 : 0;
        #pragma unroll
        for (int img = 0; img < 2; img++)
            #pragma unroll
            for (int kk = 0; kk < 2; kk++) {
                uint32_t addr = sb + (qr0 + r) * 128 + SWC(r, img * 64 + kk * 32 + c16);
                ldsm_x4(qf[img][kk], addr);
            }
    }

    float oacc[4][4];
    #pragma unroll
    for (int i = 0; i < 4; i++)
        #pragma unroll
        for (int j = 0; j < 4; j++) oacc[i][j] = 0.0f;
    float l_lo = 0.0f, l_hi = 0.0f;

    const int l2   = lane & 15;
    const int rS   = l2 & 7;
    const int c16b = (l2 & 8) ? 16 : 0;
    const float L2E = 1.4426950408889634f;

    for (int kb = 0; kb < 64; kb++) {
        const uint32_t bufK = sb + SM_BUF0 + (uint32_t)(kb & 1) * 16384u;
        const uint32_t bufV = bufK + 8192;
        CPWAIT0();
        __syncthreads();
        if (kb + 1 < 64) {
            prefetch_kv(b, kb + 1, sb + SM_BUF0 + (uint32_t)((kb + 1) & 1) * 16384u, tid);
            CPCOMMIT();
        }

        // ---- S = Q K^T (16 rows x 64 keys per warp), hi/lo compensated ----
        float sacc[8][4];
        #pragma unroll
        for (int nt = 0; nt < 8; nt++) {
            sacc[nt][0] = sacc[nt][1] = sacc[nt][2] = sacc[nt][3] = 0.0f;
            uint32_t rowaddr = bufK + (uint32_t)(nt * 8 + rS) * 128;
            #pragma unroll
            for (int kk = 0; kk < 2; kk++) {
                uint32_t kh[2], kl[2];
                ldsm_x2(kh, rowaddr + SWC(rS, kk * 32 + c16b));
                ldsm_x2(kl, rowaddr + SWC(rS, 64 + kk * 32 + c16b));
                mma16816(sacc[nt], qf[0][kk], kh);
                mma16816(sacc[nt], qf[1][kk], kh);
                mma16816(sacc[nt], qf[0][kk], kl);
            }
        }

        // ---- fixed-shift exp + row-sum ----
        #pragma unroll
        for (int nt = 0; nt < 8; nt++) {
            float p0 = ex2(fmaf(sacc[nt][0], L2E, -32.0f));
            float p1 = ex2(fmaf(sacc[nt][1], L2E, -32.0f));
            float p2 = ex2(fmaf(sacc[nt][2], L2E, -32.0f));
            float p3 = ex2(fmaf(sacc[nt][3], L2E, -32.0f));
            sacc[nt][0] = p0; sacc[nt][1] = p1; sacc[nt][2] = p2; sacc[nt][3] = p3;
            l_lo += p0 + p1;
            l_hi += p2 + p3;
        }

        // ---- O += P V (hi/lo compensated), P from accumulators ----
        #pragma unroll
        for (int kk = 0; kk < 4; kk++) {
            const float* s0 = sacc[2 * kk];
            const float* s1 = sacc[2 * kk + 1];
            uint32_t ph[4], pl[4];
            float sv[8] = { s0[0], s0[1], s0[2], s0[3], s1[0], s1[1], s1[2], s1[3] };
            #pragma unroll
            for (int i = 0; i < 4; i++) {
                float a = sv[2 * i], c = sv[2 * i + 1];
                uint32_t hw = pack2bf(a, c);
                float h0 = __uint_as_float(hw << 16);
                float h1 = __uint_as_float(hw & 0xffff0000u);
                ph[i] = hw;
                pl[i] = pack2bf(a - h0, c - h1);
            }
            #pragma unroll
            for (int nt = 0; nt < 4; nt++) {
                uint32_t vh[2], vl[2];
                ldsm_x2(vh, bufV + (uint32_t)(nt * 8 + rS) * 128      + SWC(rS, kk * 32 + c16b));
                ldsm_x2(vl, bufV + (uint32_t)(32 + nt * 8 + rS) * 128 + SWC(rS, kk * 32 + c16b));
                mma16816(oacc[nt], ph, vh);
                mma16816(oacc[nt], pl, vh);
                mma16816(oacc[nt], ph, vl);
            }
        }
    }

    // ---- normalize and stage O^T[ci][query] ----
    l_lo += __shfl_xor_sync(0xffffffffu, l_lo, 1);
    l_lo += __shfl_xor_sync(0xffffffffu, l_lo, 2);
    l_hi += __shfl_xor_sync(0xffffffffu, l_hi, 1);
    l_hi += __shfl_xor_sync(0xffffffffu, l_hi, 2);
    float inv_lo = 1.0f / l_lo;
    float inv_hi = 1.0f / l_hi;

    float* sOt = (float*)sm;
    {
        int qrow = qr0 + (lane >> 2);
        int cib  = 2 * (lane & 3);
        #pragma unroll
        for (int nt = 0; nt < 4; nt++) {
            int ci = nt * 8 + cib;
            sOt[ci * 132 + qrow]           = oacc[nt][0] * inv_lo;
            sOt[(ci + 1) * 132 + qrow]     = oacc[nt][1] * inv_lo;
            sOt[ci * 132 + qrow + 8]       = oacc[nt][2] * inv_hi;
            sOt[(ci + 1) * 132 + qrow + 8] = oacc[nt][3] * inv_hi;
        }
    }
    __syncthreads();

    // load W_out
    float* sW = (float*)(sm + SM_W);
    #pragma unroll
    for (int t = 0; t < 8; t++)
        ((float4*)sW)[tid + t * 256] = ((const float4*)Wout)[tid + t * 256];
    __syncthreads();

    // ---- epilogue: out = x + sigma * (O @ W_out) ----
    const int tx = tid & 15, ty = tid >> 4;
    const float sig = sigma_p[0];
    const uint64_t sig2 = bc2(sig);
    #pragma unroll
    for (int half = 0; half < 2; half++) {
        uint64_t eacc[4][8];
        #pragma unroll
        for (int i = 0; i < 4; i++)
            #pragma unroll
            for (int j = 0; j < 8; j++) eacc[i][j] = 0ull;
        #pragma unroll 4
        for (int c = 0; c < CI_; c++) {
            float4 o4 = *(const float4*)&sOt[c * 132 + half * 64 + ty * 4];
            uint64_t a0 = bc2(o4.x), a1 = bc2(o4.y), a2 = bc2(o4.z), a3 = bc2(o4.w);
            #pragma unroll
            for (int j = 0; j < 8; j++) {
                uint64_t w2 = *(const uint64_t*)&sW[c * C_ + 2 * tx + 32 * j];
                eacc[0][j] = f2fma(a0, w2, eacc[0][j]);
                eacc[1][j] = f2fma(a1, w2, eacc[1][j]);
                eacc[2][j] = f2fma(a2, w2, eacc[2][j]);
                eacc[3][j] = f2fma(a3, w2, eacc[3][j]);
            }
        }
        #pragma unroll
        for (int i = 0; i < 4; i++) {
            size_t rowoff = ((size_t)b * N_ + qt * 128 + half * 64 + ty * 4 + i) * C_;
            #pragma unroll
            for (int j = 0; j < 8; j++) {
                size_t off = rowoff + 2 * tx + 32 * j;
                uint64_t x2 = *(const uint64_t*)&x[off];
                *(uint64_t*)&outp[off] = f2fma(sig2, eacc[i][j], x2);
            }
        }
    }
}

// ---------------- launch ----------------
extern "C" void kernel_launch(void* const* d_in, const int* in_sizes, int n_in,
                              void* d_out, int out_size)
{
    (void)in_sizes; (void)n_in; (void)out_size;
    const float* x     = (const float*)d_in[0];
    const float* y     = (const float*)d_in[1];
    const float* Wfy   = (const float*)d_in[2];
    const float* Wgx   = (const float*)d_in[3];
    const float* Whx   = (const float*)d_in[4];
    const float* Wout  = (const float*)d_in[5];
    const float* sigma = (const float*)d_in[6];
    float* out = (float*)d_out;

    static int attr_set = 0;
    if (!attr_set) {
        cudaFuncSetAttribute(attn_kernel, cudaFuncAttributeMaxDynamicSharedMemorySize, SM_TOT);
        attr_set = 1;
    }
    proj_kernel<<<dim3((B_ * N_) / 64, 3), 256>>>(x, y, Wfy, Wgx, Whx);
    attn_kernel<<<dim3(N_ / 128, B_), 256, SM_TOT>>>(x, Wout, sigma, out);
}

// round 7
// speedup vs baseline: 3.9124x; 1.3173x over previous
#include <cuda_runtime.h>
#include <cuda_bf16.h>
#include <cstdint>
#include <cstddef>

#define B_   8
#define N_   4096
#define C_   256
#define CI_  32

// Global bf16 scratch written by proj_kernel:
// g_q/g_k per global row r (= b*4096+n): 128B = 64 bf16: ci 0..31 hi at bytes 0..63, lo at 64..127
//   (g_q is pre-scaled by log2(e))
// g_v: V^T per batch: [32 rows: ci hi][4096 keys] bf16 (no lo image needed)
__device__ uint4 g_q[262144];
__device__ uint4 g_k[262144];
__device__ uint4 g_v[131072];

// ---------------- fp32x2 helpers ----------------
__device__ __forceinline__ uint64_t pk2(float lo, float hi) {
    uint64_t r; asm("mov.b64 %0,{%1,%2};" : "=l"(r) : "f"(lo), "f"(hi)); return r;
}
__device__ __forceinline__ uint64_t bc2(float v) { return pk2(v, v); }
__device__ __forceinline__ void up2(uint64_t p, float &lo, float &hi) {
    asm("mov.b64 {%0,%1},%2;" : "=f"(lo), "=f"(hi) : "l"(p));
}
__device__ __forceinline__ uint64_t f2fma(uint64_t a, uint64_t b, uint64_t c) {
    uint64_t d; asm("fma.rn.f32x2 %0,%1,%2,%3;" : "=l"(d) : "l"(a), "l"(b), "l"(c)); return d;
}

// ---------------- misc helpers ----------------
__device__ __forceinline__ uint32_t smem_u32(const void* p) {
    uint32_t a;
    asm("{ .reg .u64 t; cvta.to.shared.u64 t, %1; cvt.u32.u64 %0, t; }" : "=r"(a) : "l"(p));
    return a;
}
// pack two fp32 -> bf16x2; 'lo' in low 16 bits
__device__ __forceinline__ uint32_t pack2bf(float lo, float hi) {
    uint32_t r; asm("cvt.rn.bf16x2.f32 %0, %1, %2;" : "=r"(r) : "f"(hi), "f"(lo)); return r;
}
__device__ __forceinline__ float ex2(float t) {
    float p; asm("ex2.approx.ftz.f32 %0, %1;" : "=f"(p) : "f"(t)); return p;
}

// byte-column swizzle within a 128B row (SW128 pattern)
#define SWC(row, colb) ((uint32_t)((colb) ^ (((row) & 7) << 4)))

#define CP16(dst, src) \
    asm volatile("cp.async.ca.shared.global [%0], [%1], 16;" :: "r"(dst), "l"(src))
#define CPCOMMIT() asm volatile("cp.async.commit_group;" ::: "memory")
#define CPWAIT0()  asm volatile("cp.async.wait_group 0;" ::: "memory")

__device__ __forceinline__ void ldsm_x4(uint32_t* r, uint32_t addr) {
    asm volatile("ldmatrix.sync.aligned.m8n8.x4.shared.b16 {%0,%1,%2,%3}, [%4];"
        : "=r"(r[0]), "=r"(r[1]), "=r"(r[2]), "=r"(r[3]) : "r"(addr));
}
__device__ __forceinline__ void mma16816(float* c, const uint32_t* a, const uint32_t* b) {
    asm volatile(
        "mma.sync.aligned.m16n8k16.row.col.f32.bf16.bf16.f32 "
        "{%0,%1,%2,%3}, {%4,%5,%6,%7}, {%8,%9}, {%0,%1,%2,%3};"
        : "+f"(c[0]), "+f"(c[1]), "+f"(c[2]), "+f"(c[3])
        : "r"(a[0]), "r"(a[1]), "r"(a[2]), "r"(a[3]), "r"(b[0]), "r"(b[1]));
}

// ---------------- Kernel 1: fused projections -> bf16 hi/lo global tiles ----------------
// grid (512, 2): y==0: Q from y-input (scaled by log2 e); y==1: K and V from x (x read once)
#define TSTR 68
__global__ void __launch_bounds__(256, 2) proj_kernel(
    const float* __restrict__ x, const float* __restrict__ y,
    const float* __restrict__ Wfy, const float* __restrict__ Wgx,
    const float* __restrict__ Whx)
{
    __shared__ float sA[32 * TSTR];
    __shared__ float sW[2 * 32 * 32];

    const int tid = threadIdx.x;
    const int tx  = tid & 15;
    const int ty  = tid >> 4;
    const int pass = blockIdx.y;

    const float* A = (pass == 0) ? y : x;
    const int row0 = blockIdx.x * 64;

    uint64_t accA[4] = {0ull, 0ull, 0ull, 0ull};  // Q or K
    uint64_t accV[4] = {0ull, 0ull, 0ull, 0ull};  // V (pass 1 only)

    for (int kc = 0; kc < C_; kc += 32) {
        __syncthreads();
        #pragma unroll
        for (int t = 0; t < 8; t++) {
            int idx = tid + t * 256;
            int r = idx >> 5, k = idx & 31;
            sA[k * TSTR + r] = A[(size_t)(row0 + r) * C_ + kc + k];
        }
        if (pass == 0) {
            #pragma unroll
            for (int t = 0; t < 4; t++) {
                int idx = tid + t * 256;
                int kr = idx >> 5, c = idx & 31;
                sW[kr * 32 + c] = Wfy[(size_t)(kc + kr) * CI_ + c];
            }
        } else {
            #pragma unroll
            for (int t = 0; t < 8; t++) {
                int idx = tid + t * 256;
                int half = idx >> 10;           // 0: Wgx, 1: Whx
                int kr = (idx >> 5) & 31, c = idx & 31;
                const float* Wsrc = half ? Whx : Wgx;
                sW[half * 1024 + kr * 32 + c] = Wsrc[(size_t)(kc + kr) * CI_ + c];
            }
        }
        __syncthreads();

        if (pass == 0) {
            #pragma unroll 8
            for (int k = 0; k < 32; k++) {
                float4 a4 = *(const float4*)&sA[k * TSTR + ty * 4];
                uint64_t b = *(const uint64_t*)&sW[k * 32 + 2 * tx];
                accA[0] = f2fma(bc2(a4.x), b, accA[0]);
                accA[1] = f2fma(bc2(a4.y), b, accA[1]);
                accA[2] = f2fma(bc2(a4.z), b, accA[2]);
                accA[3] = f2fma(bc2(a4.w), b, accA[3]);
            }
        } else {
            #pragma unroll 8
            for (int k = 0; k < 32; k++) {
                float4 a4 = *(const float4*)&sA[k * TSTR + ty * 4];
                uint64_t bg = *(const uint64_t*)&sW[k * 32 + 2 * tx];
                uint64_t bh = *(const uint64_t*)&sW[1024 + k * 32 + 2 * tx];
                uint64_t a0 = bc2(a4.x), a1 = bc2(a4.y), a2 = bc2(a4.z), a3 = bc2(a4.w);
                accA[0] = f2fma(a0, bg, accA[0]);
                accA[1] = f2fma(a1, bg, accA[1]);
                accA[2] = f2fma(a2, bg, accA[2]);
                accA[3] = f2fma(a3, bg, accA[3]);
                accV[0] = f2fma(a0, bh, accV[0]);
                accV[1] = f2fma(a1, bh, accV[1]);
                accV[2] = f2fma(a2, bh, accV[2]);
                accV[3] = f2fma(a3, bh, accV[3]);
            }
        }
    }

    const float L2E = 1.4426950408889634f;
    if (pass == 0) {
        uint32_t* out = (uint32_t*)g_q;
        #pragma unroll
        for (int i = 0; i < 4; i++) {
            size_t r = (size_t)(row0 + ty * 4 + i);
            float v0, v1; up2(accA[i], v0, v1);
            v0 *= L2E; v1 *= L2E;
            uint32_t hw = pack2bf(v0, v1);
            float h0 = __uint_as_float(hw << 16);
            float h1 = __uint_as_float(hw & 0xffff0000u);
            uint32_t lw = pack2bf(v0 - h0, v1 - h1);
            out[r * 32 + tx]      = hw;
            out[r * 32 + 16 + tx] = lw;
        }
    } else {
        uint32_t* outk = (uint32_t*)g_k;
        unsigned short* outv = (unsigned short*)g_v;
        #pragma unroll
        for (int i = 0; i < 4; i++) {
            size_t r = (size_t)(row0 + ty * 4 + i);
            float v0, v1; up2(accA[i], v0, v1);
            uint32_t hw = pack2bf(v0, v1);
            float h0 = __uint_as_float(hw << 16);
            float h1 = __uint_as_float(hw & 0xffff0000u);
            uint32_t lw = pack2bf(v0 - h0, v1 - h1);
            outk[r * 32 + tx]      = hw;
            outk[r * 32 + 16 + tx] = lw;

            int rg = row0 + ty * 4 + i;
            int bq = rg >> 12, key = rg & 4095;
            float w0, w1; up2(accV[i], w0, w1);
            uint32_t vp = pack2bf(w0, w1);
            outv[((size_t)(bq * 32 + 2 * tx)     * 4096) + key] = (unsigned short)(vp & 0xffffu);
            outv[((size_t)(bq * 32 + 2 * tx + 1) * 4096) + key] = (unsigned short)(vp >> 16);
        }
    }
}

// ---------------- Kernel 2: warp-MMA flash attention + fused epilogue ----------------
// smem: sQ @0 (16KB); buf0 @16384 (K 8KB + V 4KB); buf1 @28672 (12KB); end 40960
// epilogue overlay: sOt fp32 @0 (32 x 132 = 16896B), sW fp32 @17408 (32KB). Total 50176.
#define SM_BUF0 16384
#define SM_STG  12288
#define SM_W    17408
#define SM_TOT  50176

__device__ __forceinline__ void prefetch_kv(int b, int kb, uint32_t bufbase, int tid) {
    #pragma unroll
    for (int t = 0; t < 3; t++) {
        int idx = tid + t * 256;
        if (idx < 512) {  // K tile: 64 key-rows x 128B (hi+lo)
            int row = idx >> 3, ch = idx & 7;
            uint32_t dst = bufbase + row * 128 + SWC(row, ch * 16);
            const uint4* src = g_k + ((size_t)(b * 4096 + kb * 64 + row) * 8 + ch);
            CP16(dst, src);
        } else {          // V tile: 32 ci-rows x 128B (64 keys, hi only)
            int j = idx - 512;
            int row = j >> 3, ch = j & 7;
            uint32_t dst = bufbase + 8192 + row * 128 + SWC(row, ch * 16);
            const uint4* src = g_v + ((size_t)(b * 32 + row) * 512 + (size_t)kb * 8 + ch);
            CP16(dst, src);
        }
    }
}

__global__ void __launch_bounds__(256, 2) attn_kernel(
    const float* __restrict__ x, const float* __restrict__ Wout,
    const float* __restrict__ sigma_p, float* __restrict__ outp)
{
    extern __shared__ unsigned char sm[];
    const uint32_t sb = smem_u32(sm);

    const int tid  = threadIdx.x;
    const int lane = tid & 31;
    const int w    = tid >> 5;       // warp 0..7 -> query rows 16w..16w+15
    const int qt   = blockIdx.x;
    const int b    = blockIdx.y;
    const int qr0  = w * 16;

    prefetch_kv(b, 0, sb + SM_BUF0, tid);
    CPCOMMIT();

    // load Q tile (swizzled)
    {
        const uint4* src = g_q + (size_t)(b * 4096 + qt * 128) * 8;
        #pragma unroll
        for (int t = 0; t < 4; t++) {
            int idx = tid + t * 256;
            int row = idx >> 3, ch = idx & 7;
            *(uint4*)(sm + row * 128 + SWC(row, ch * 16)) = src[idx];
        }
    }
    __syncthreads();

    // Q fragments: [img hi/lo][kstep][4 regs]
    uint32_t qf[2][2][4];
    {
        int r = lane & 15;
        int c16 = (lane >= 16) ? 16 : 0;
        #pragma unroll
        for (int img = 0; img < 2; img++)
            #pragma unroll
            for (int kk = 0; kk < 2; kk++) {
                uint32_t addr = sb + (qr0 + r) * 128 + SWC(r, img * 64 + kk * 32 + c16);
                ldsm_x4(qf[img][kk], addr);
            }
    }

    float oacc[4][4];
    #pragma unroll
    for (int i = 0; i < 4; i++)
        #pragma unroll
        for (int j = 0; j < 4; j++) oacc[i][j] = 0.0f;
    float l_lo = 0.0f, l_hi = 0.0f;

    // full-lane ldmatrix x4 addressing: matrices 0,1 = rows +0..7 (cols +0,+16),
    // matrices 2,3 = rows +8..15 (cols +0,+16)
    const int rB = (lane & 7) | ((lane & 16) >> 1);   // 0..15
    const int cB = (lane & 8) ? 16 : 0;

    for (int kb = 0; kb < 64; kb++) {
        const uint32_t bufK = sb + SM_BUF0 + (uint32_t)(kb & 1) * SM_STG;
        const uint32_t bufV = bufK + 8192;
        CPWAIT0();
        __syncthreads();
        if (kb + 1 < 64) {
            prefetch_kv(b, kb + 1, sb + SM_BUF0 + (uint32_t)((kb + 1) & 1) * SM_STG, tid);
            CPCOMMIT();
        }

        // ---- S = Q K^T (16 rows x 64 keys per warp), 3-product hi/lo ----
        float sacc[8][4];
        #pragma unroll
        for (int ntp = 0; ntp < 4; ntp++) {
            float* s0 = sacc[2 * ntp];
            float* s1 = sacc[2 * ntp + 1];
            s0[0] = s0[1] = s0[2] = s0[3] = 0.0f;
            s1[0] = s1[1] = s1[2] = s1[3] = 0.0f;
            uint32_t rowaddr = bufK + (uint32_t)(ntp * 16 + rB) * 128;
            #pragma unroll
            for (int kk = 0; kk < 2; kk++) {
                uint32_t kh[4], kl[4];
                ldsm_x4(kh, rowaddr + SWC(rB, kk * 32 + cB));
                ldsm_x4(kl, rowaddr + SWC(rB, 64 + kk * 32 + cB));
                mma16816(s0, qf[0][kk], kh);
                mma16816(s0, qf[1][kk], kh);
                mma16816(s0, qf[0][kk], kl);
                mma16816(s1, qf[0][kk], kh + 2);
                mma16816(s1, qf[1][kk], kh + 2);
                mma16816(s1, qf[0][kk], kl + 2);
            }
        }

        // ---- exp (no shift; 2^s factor cancels in normalization) ----
        #pragma unroll
        for (int nt = 0; nt < 8; nt++) {
            float p0 = ex2(sacc[nt][0]);
            float p1 = ex2(sacc[nt][1]);
            float p2 = ex2(sacc[nt][2]);
            float p3 = ex2(sacc[nt][3]);
            sacc[nt][0] = p0; sacc[nt][1] = p1; sacc[nt][2] = p2; sacc[nt][3] = p3;
            l_lo += p0 + p1;
            l_hi += p2 + p3;
        }

        // ---- O += P V (single product) ----
        #pragma unroll
        for (int kk = 0; kk < 4; kk++) {
            const float* s0 = sacc[2 * kk];
            const float* s1 = sacc[2 * kk + 1];
            uint32_t ph[4];
            ph[0] = pack2bf(s0[0], s0[1]);
            ph[1] = pack2bf(s0[2], s0[3]);
            ph[2] = pack2bf(s1[0], s1[1]);
            ph[3] = pack2bf(s1[2], s1[3]);
            #pragma unroll
            for (int ntp = 0; ntp < 2; ntp++) {
                uint32_t vh[4];
                ldsm_x4(vh, bufV + (uint32_t)(ntp * 16 + rB) * 128 + SWC(rB, kk * 32 + cB));
                mma16816(oacc[2 * ntp],     ph, vh);
                mma16816(oacc[2 * ntp + 1], ph, vh + 2);
            }
        }
    }

    // ---- normalize and stage O^T[ci][query] ----
    l_lo += __shfl_xor_sync(0xffffffffu, l_lo, 1);
    l_lo += __shfl_xor_sync(0xffffffffu, l_lo, 2);
    l_hi += __shfl_xor_sync(0xffffffffu, l_hi, 1);
    l_hi += __shfl_xor_sync(0xffffffffu, l_hi, 2);
    float inv_lo = 1.0f / l_lo;
    float inv_hi = 1.0f / l_hi;

    float* sOt = (float*)sm;
    __syncthreads();   // buffers dead; reuse smem
    {
        int qrow = qr0 + (lane >> 2);
        int cib  = 2 * (lane & 3);
        #pragma unroll
        for (int nt = 0; nt < 4; nt++) {
            int ci = nt * 8 + cib;
            sOt[ci * 132 + qrow]           = oacc[nt][0] * inv_lo;
            sOt[(ci + 1) * 132 + qrow]     = oacc[nt][1] * inv_lo;
            sOt[ci * 132 + qrow + 8]       = oacc[nt][2] * inv_hi;
            sOt[(ci + 1) * 132 + qrow + 8] = oacc[nt][3] * inv_hi;
        }
    }

    // load W_out
    float* sW = (float*)(sm + SM_W);
    #pragma unroll
    for (int t = 0; t < 8; t++)
        ((float4*)sW)[tid + t * 256] = ((const float4*)Wout)[tid + t * 256];
    __syncthreads();

    // ---- epilogue: out = x + sigma * (O @ W_out) ----
    const int tx = tid & 15, ty = tid >> 4;
    const float sig = sigma_p[0];
    const uint64_t sig2 = bc2(sig);
    #pragma unroll
    for (int half = 0; half < 2; half++) {
        uint64_t eacc[4][8];
        #pragma unroll
        for (int i = 0; i < 4; i++)
            #pragma unroll
            for (int j = 0; j < 8; j++) eacc[i][j] = 0ull;
        #pragma unroll 4
        for (int c = 0; c < CI_; c++) {
            float4 o4 = *(const float4*)&sOt[c * 132 + half * 64 + ty * 4];
            uint64_t a0 = bc2(o4.x), a1 = bc2(o4.y), a2 = bc2(o4.z), a3 = bc2(o4.w);
            #pragma unroll
            for (int j = 0; j < 8; j++) {
                uint64_t w2 = *(const uint64_t*)&sW[c * C_ + 2 * tx + 32 * j];
                eacc[0][j] = f2fma(a0, w2, eacc[0][j]);
                eacc[1][j] = f2fma(a1, w2, eacc[1][j]);
                eacc[2][j] = f2fma(a2, w2, eacc[2][j]);
                eacc[3][j] = f2fma(a3, w2, eacc[3][j]);
            }
        }
        #pragma unroll
        for (int i = 0; i < 4; i++) {
            size_t rowoff = ((size_t)b * N_ + qt * 128 + half * 64 + ty * 4 + i) * C_;
            #pragma unroll
            for (int j = 0; j < 8; j++) {
                size_t off = rowoff + 2 * tx + 32 * j;
                uint64_t x2 = *(const uint64_t*)&x[off];
                *(uint64_t*)&outp[off] = f2fma(sig2, eacc[i][j], x2);
            }
        }
    }
}

// ---------------- launch ----------------
extern "C" void kernel_launch(void* const* d_in, const int* in_sizes, int n_in,
                              void* d_out, int out_size)
{
    (void)in_sizes; (void)n_in; (void)out_size;
    const float* x     = (const float*)d_in[0];
    const float* y     = (const float*)d_in[1];
    const float* Wfy   = (const float*)d_in[2];
    const float* Wgx   = (const float*)d_in[3];
    const float* Whx   = (const float*)d_in[4];
    const float* Wout  = (const float*)d_in[5];
    const float* sigma = (const float*)d_in[6];
    float* out = (float*)d_out;

    static int attr_set = 0;
    if (!attr_set) {
        cudaFuncSetAttribute(attn_kernel, cudaFuncAttributeMaxDynamicSharedMemorySize, SM_TOT);
        attr_set = 1;
    }
    proj_kernel<<<dim3((B_ * N_) / 64, 2), 256>>>(x, y, Wfy, Wgx, Whx);
    attn_kernel<<<dim3(N_ / 128, B_), 256, SM_TOT>>>(x, Wout, sigma, out);
}